// round 6
// baseline (speedup 1.0000x reference)
#include <cuda_runtime.h>
#include <cuda_fp16.h>
#include <cstdint>
#include <math.h>

// ---------------- problem constants ----------------
#define TOTAL    4096
#define DDIM     512
#define NPAIRS   2048
#define KAUG     576          // 512 dims + 64 label one-hot dims
#define NT       32           // 4096/128 tile grid
#define NTILES   528          // NT*(NT+1)/2 upper-triangular tiles
#define BT       128
#define KCHUNK   64           // f16 elems per K chunk (128 bytes per smem row)
#define NCHUNKS  9            // 576 / 64
#define INV_T    (1.0f/0.07f)
// sqrt( (1/0.07) * log2(e) ): operands pre-scaled so accumulator is log2-units
#define SCALE_LOG2 4.539816f

// ---------------- device scratch ----------------
__device__ __half g_row[TOTAL * KAUG];  // scaled + (+16)*onehot(label)
__device__ __half g_col[TOTAL * KAUG];  // scaled + (-8)*onehot(label)
__device__ float  g_pos[NPAIRS];
__device__ double g_neg;
__device__ int    g_cnt;

// ---------------- asm helpers (sm_80-era PTX only) ----------------
__device__ __forceinline__ uint32_t smem_u32(const void* p) {
    return (uint32_t)__cvta_generic_to_shared(p);
}
__device__ __forceinline__ uint32_t h2_bits(__half2 h) {
    return *reinterpret_cast<uint32_t*>(&h);
}
__device__ __forceinline__ void ldmatrix_x4(uint32_t* r, uint32_t addr) {
    asm volatile("ldmatrix.sync.aligned.m8n8.x4.shared.b16 {%0,%1,%2,%3}, [%4];"
        : "=r"(r[0]), "=r"(r[1]), "=r"(r[2]), "=r"(r[3]) : "r"(addr));
}
// f16 accumulate: D (2x f16x2 regs) = A(4) * B(2) + D
__device__ __forceinline__ void mma16816_f16(uint32_t* c, const uint32_t* a,
                                             uint32_t b0, uint32_t b1) {
    asm volatile(
        "mma.sync.aligned.m16n8k16.row.col.f16.f16.f16.f16 "
        "{%0,%1}, {%2,%3,%4,%5}, {%6,%7}, {%0,%1};"
        : "+r"(c[0]), "+r"(c[1])
        : "r"(a[0]), "r"(a[1]), "r"(a[2]), "r"(a[3]), "r"(b0), "r"(b1));
}
#define CP_ASYNC16(so, gp) \
    asm volatile("cp.async.cg.shared.global [%0], [%1], 16;" :: "r"(so), "l"(gp))
#define CP_COMMIT()  asm volatile("cp.async.commit_group;" ::: "memory")
#define CP_WAIT(n)   asm volatile("cp.async.wait_group %0;" :: "n"(n) : "memory")

// fast exp2 on log2-unit accumulators (masked lanes ~ -107, clamped to -100)
__device__ __forceinline__ float exp2_fast(float tv) {
    tv = fmaxf(tv, -100.0f);
    float rr = tv + 12582912.0f;            // round-to-nearest-int magic (1.5*2^23)
    float kf = rr - 12582912.0f;
    float f  = tv - kf;                     // f in [-0.5, 0.5]
    float p  = fmaf(f, 0.009618129f, 0.05550411f);
    p = fmaf(f, p, 0.24022651f);
    p = fmaf(f, p, 0.69314718f);
    p = fmaf(f, p, 1.0f);                   // ~= 2^f
    return __int_as_float((__float_as_int(rr) << 23) + __float_as_int(p));
}

// ---------------------------------------------------------------------------
// 1) prep+pos: one block per augmentation pair (rows 2p, 2p+1).
// ---------------------------------------------------------------------------
__global__ void prep_kernel(const float* __restrict__ E, const int* __restrict__ labels) {
    int pair = blockIdx.x;
    int tid  = threadIdx.x;       // 128 threads
    int lane = tid & 31, wid = tid >> 5;

    const float4* A = reinterpret_cast<const float4*>(E + (size_t)(2 * pair) * DDIM);
    const float4* B = A + DDIM / 4;
    float4 a = A[tid], b = B[tid];
    float aa = a.x*a.x + a.y*a.y + a.z*a.z + a.w*a.w;
    float bb = b.x*b.x + b.y*b.y + b.z*b.z + b.w*b.w;
    float ab = a.x*b.x + a.y*b.y + a.z*b.z + a.w*b.w;
    #pragma unroll
    for (int off = 16; off > 0; off >>= 1) {
        aa += __shfl_down_sync(0xffffffffu, aa, off);
        bb += __shfl_down_sync(0xffffffffu, bb, off);
        ab += __shfl_down_sync(0xffffffffu, ab, off);
    }
    __shared__ float s_aa[4], s_bb[4], s_ab[4];
    if (lane == 0) { s_aa[wid] = aa; s_bb[wid] = bb; s_ab[wid] = ab; }
    __syncthreads();
    float taa = s_aa[0] + s_aa[1] + s_aa[2] + s_aa[3];
    float tbb = s_bb[0] + s_bb[1] + s_bb[2] + s_bb[3];
    float tab = s_ab[0] + s_ab[1] + s_ab[2] + s_ab[3];
    float sa = rsqrtf(taa) * SCALE_LOG2;
    float sb = rsqrtf(tbb) * SCALE_LOG2;

    size_t baseA = (size_t)(2 * pair) * KAUG + tid * 4;
    size_t baseB = baseA + KAUG;
    uint2 pa, pb;
    pa.x = h2_bits(__floats2half2_rn(a.x * sa, a.y * sa));
    pa.y = h2_bits(__floats2half2_rn(a.z * sa, a.w * sa));
    pb.x = h2_bits(__floats2half2_rn(b.x * sb, b.y * sb));
    pb.y = h2_bits(__floats2half2_rn(b.z * sb, b.w * sb));
    *reinterpret_cast<uint2*>(g_row + baseA) = pa;
    *reinterpret_cast<uint2*>(g_col + baseA) = pa;
    *reinterpret_cast<uint2*>(g_row + baseB) = pb;
    *reinterpret_cast<uint2*>(g_col + baseB) = pb;

    if (tid < 64) {
        int lab = labels[pair];
        __half hr = __float2half(tid == lab ? 16.0f : 0.0f);
        __half hc = __float2half(tid == lab ? -8.0f : 0.0f);
        size_t oA = (size_t)(2 * pair) * KAUG + DDIM + tid;
        g_row[oA] = hr;          g_col[oA] = hc;
        g_row[oA + KAUG] = hr;   g_col[oA + KAUG] = hc;
    }
    if (tid == 0) {
        g_pos[pair] = tab * rsqrtf(taa * tbb) * INV_T;
        if (pair == 0) { g_neg = 0.0; g_cnt = 0; }
    }
}

// ---------------------------------------------------------------------------
// 2) HMMA f16-acc GEMM, 128x128 CTA tile, 8 warps (64x32 each) for occupancy:
//    4 warps/SMSP at 2 CTAs/SM hides LDSM->MMA latency (R5 was 2/SMSP, tensor
//    pipe only 38.8% busy). cp.async double buffering; exp2-sum epilogue on
//    register accumulators; last CTA computes the final loss.
// ---------------------------------------------------------------------------
__device__ __forceinline__ void load_chunk(uint32_t sb, int tid, int row0, int col0,
                                           int c, int buf) {
    #pragma unroll
    for (int itv = 0; itv < 8; itv++) {
        int slot = itv * 256 + tid;           // 0..2047 16B transfers
        int isB  = slot >> 10;
        int s2   = slot & 1023;
        int r    = s2 >> 3;                   // row in tile (0..127)
        int g    = s2 & 7;                    // 16B group in 128B row
        const __half* src = isB
            ? (g_col + (size_t)(col0 + r) * KAUG)
            : (g_row + (size_t)(row0 + r) * KAUG);
        src += c * KCHUNK + g * 8;
        uint32_t so = sb + buf * 32768 + isB * 16384
                    + (uint32_t)(r * 128) + (uint32_t)((g * 16) ^ ((r & 7) * 16));
        CP_ASYNC16(so, src);
    }
    CP_COMMIT();
}

__global__ void __launch_bounds__(256, 2) gemm_negsum_kernel(float* __restrict__ out) {
    extern __shared__ char smem[];
    __shared__ float red[8];
    __shared__ int   lastflag;
    uint32_t sb = smem_u32(smem);

    int tid  = threadIdx.x;
    int lane = tid & 31;
    int wid  = tid >> 5;

    // triangular tile decode
    int t = blockIdx.x, bi = 0, rem = NT;
    while (t >= rem) { t -= rem; rem--; bi++; }
    int bj = bi + t;
    int row0 = bi * BT, col0 = bj * BT;

    load_chunk(sb, tid, row0, col0, 0, 0);
    load_chunk(sb, tid, row0, col0, 1, 1);

    // warp tile: 64 (m) x 32 (n); 2 warps in m, 4 in n
    int wm0 = (wid & 1) * 64;
    int wn0 = (wid >> 1) * 32;

    int arow = wm0 + (lane & 15);
    uint32_t a_xor = (uint32_t)((arow & 7) * 16);
    uint32_t a_colbase = (uint32_t)((lane >> 4) * 16);
    int brow = wn0 + ((lane >> 4) & 1) * 8 + (lane & 7);
    uint32_t b_xor = (uint32_t)((brow & 7) * 16);
    uint32_t b_colbase = (uint32_t)(((lane >> 3) & 1) * 16);

    uint32_t acc[4][4][2];                    // f16x2 accumulators (64x32)
    #pragma unroll
    for (int i = 0; i < 4; i++)
        #pragma unroll
        for (int j = 0; j < 4; j++) { acc[i][j][0] = 0u; acc[i][j][1] = 0u; }

    for (int c = 0; c < NCHUNKS; c++) {
        int buf = c & 1;
        if (c == NCHUNKS - 1) { CP_WAIT(0); } else { CP_WAIT(1); }
        __syncthreads();

        uint32_t Ab = sb + (uint32_t)(buf * 32768);
        uint32_t Bb = Ab + 16384;
        #pragma unroll
        for (int ks = 0; ks < 4; ks++) {
            uint32_t a[4][4];
            uint32_t acol = (uint32_t)(ks * 32) + a_colbase;
            #pragma unroll
            for (int mt = 0; mt < 4; mt++)
                ldmatrix_x4(a[mt], Ab + (uint32_t)((arow + mt * 16) * 128) + (acol ^ a_xor));

            uint32_t b[2][4];
            uint32_t bcol = (uint32_t)(ks * 32) + b_colbase;
            #pragma unroll
            for (int p = 0; p < 2; p++)
                ldmatrix_x4(b[p], Bb + (uint32_t)((brow + p * 16) * 128) + (bcol ^ b_xor));

            #pragma unroll
            for (int mt = 0; mt < 4; mt++)
                #pragma unroll
                for (int nt = 0; nt < 4; nt++)
                    mma16816_f16(acc[mt][nt], a[mt],
                                 b[nt >> 1][(nt & 1) * 2 + 0],
                                 b[nt >> 1][(nt & 1) * 2 + 1]);
        }
        __syncthreads();
        if (c + 2 < NCHUNKS) load_chunk(sb, tid, row0, col0, c + 2, buf);
    }

    // ---- epilogue: exp2 over all 64 f16 accumulators ----
    float lsum = 0.0f;
    #pragma unroll
    for (int mt = 0; mt < 4; mt++)
        #pragma unroll
        for (int nt = 0; nt < 4; nt++)
            #pragma unroll
            for (int e = 0; e < 2; e++) {
                float2 v = __half22float2(*reinterpret_cast<__half2*>(&acc[mt][nt][e]));
                lsum += exp2_fast(v.x);
                lsum += exp2_fast(v.y);
            }
    if (bi == bj) lsum *= 0.5f;               // diagonal tile counts pairs twice

    #pragma unroll
    for (int off = 16; off > 0; off >>= 1) lsum += __shfl_down_sync(0xffffffffu, lsum, off);
    if (lane == 0) red[wid] = lsum;
    __syncthreads();
    if (tid == 0) {
        float s = 0.0f;
        #pragma unroll
        for (int w = 0; w < 8; w++) s += red[w];
        atomicAdd(&g_neg, (double)s);
        __threadfence();
        lastflag = (atomicAdd(&g_cnt, 1) == NTILES - 1);
    }
    __syncthreads();

    // ---- last CTA computes the final loss ----
    if (lastflag) {
        __threadfence();
        float negf = (float)g_neg;
        float s = 0.0f;
        for (int p = tid; p < NPAIRS; p += 256) {
            float sp = g_pos[p];
            s += __logf(__expf(sp) + negf) - sp;
        }
        #pragma unroll
        for (int off = 16; off > 0; off >>= 1) s += __shfl_down_sync(0xffffffffu, s, off);
        if (lane == 0) red[wid] = s;
        __syncthreads();
        if (tid == 0) {
            float tot = 0.0f;
            #pragma unroll
            for (int w = 0; w < 8; w++) tot += red[w];
            out[0] = tot / (float)NPAIRS;
            g_cnt = 0;
        }
    }
}

// ---------------------------------------------------------------------------
extern "C" void kernel_launch(void* const* d_in, const int* in_sizes, int n_in,
                              void* d_out, int out_size) {
    const float* E      = (const float*)d_in[0];
    const int*   labels = (const int*)d_in[1];
    float*       out    = (float*)d_out;

    const int SMEM_BYTES = 2 * 32768;   // double-buffered A+B tiles
    cudaFuncSetAttribute(gemm_negsum_kernel,
                         cudaFuncAttributeMaxDynamicSharedMemorySize, SMEM_BYTES);

    prep_kernel<<<NPAIRS, 128>>>(E, labels);
    gemm_negsum_kernel<<<NTILES, 256, SMEM_BYTES>>>(out);
}

// round 7
// speedup vs baseline: 1.1509x; 1.1509x over previous
#include <cuda_runtime.h>
#include <cuda_fp16.h>
#include <cstdint>
#include <math.h>

// ---------------- problem constants ----------------
#define TOTAL    4096
#define DDIM     512
#define NPAIRS   2048
#define KAUG     576          // 512 dims + 64 label one-hot dims
#define NT       32           // 4096/128 tile grid
#define NTILES   528          // NT*(NT+1)/2 upper-triangular tiles
#define BT       128
#define KCHUNK   64           // f16 elems per K chunk (128 bytes per smem row)
#define NCHUNKS  9            // 576 / 64
#define INV_T    (1.0f/0.07f)
// sqrt( (1/0.07) * log2(e) ): operands pre-scaled so accumulator is log2-units
#define SCALE_LOG2 4.539816f

#define BUF_BYTES 32768       // A(16KB)+B(16KB) per stage
#define NSTAGES   3

// ---------------- device scratch ----------------
__device__ __half g_row[TOTAL * KAUG];  // scaled + (+16)*onehot(label)
__device__ __half g_col[TOTAL * KAUG];  // scaled + (-8)*onehot(label)
__device__ float  g_pos[NPAIRS];
__device__ double g_neg;
__device__ int    g_cnt;

// ---------------- asm helpers (sm_80-era PTX only) ----------------
__device__ __forceinline__ uint32_t smem_u32(const void* p) {
    return (uint32_t)__cvta_generic_to_shared(p);
}
__device__ __forceinline__ uint32_t h2_bits(__half2 h) {
    return *reinterpret_cast<uint32_t*>(&h);
}
__device__ __forceinline__ void ldmatrix_x4(uint32_t* r, uint32_t addr) {
    asm volatile("ldmatrix.sync.aligned.m8n8.x4.shared.b16 {%0,%1,%2,%3}, [%4];"
        : "=r"(r[0]), "=r"(r[1]), "=r"(r[2]), "=r"(r[3]) : "r"(addr));
}
// f16 accumulate: D (2x f16x2 regs) = A(4) * B(2) + D
__device__ __forceinline__ void mma16816_f16(uint32_t* c, const uint32_t* a,
                                             uint32_t b0, uint32_t b1) {
    asm volatile(
        "mma.sync.aligned.m16n8k16.row.col.f16.f16.f16.f16 "
        "{%0,%1}, {%2,%3,%4,%5}, {%6,%7}, {%0,%1};"
        : "+r"(c[0]), "+r"(c[1])
        : "r"(a[0]), "r"(a[1]), "r"(a[2]), "r"(a[3]), "r"(b0), "r"(b1));
}
#define CP_ASYNC16(so, gp) \
    asm volatile("cp.async.cg.shared.global [%0], [%1], 16;" :: "r"(so), "l"(gp))
#define CP_COMMIT()  asm volatile("cp.async.commit_group;" ::: "memory")
#define CP_WAIT(n)   asm volatile("cp.async.wait_group %0;" :: "n"(n) : "memory")

// fast exp2 on log2-unit accumulators (masked lanes ~ -107, clamped to -100)
__device__ __forceinline__ float exp2_fast(float tv) {
    tv = fmaxf(tv, -100.0f);
    float rr = tv + 12582912.0f;            // round-to-nearest-int magic (1.5*2^23)
    float kf = rr - 12582912.0f;
    float f  = tv - kf;                     // f in [-0.5, 0.5]
    float p  = fmaf(f, 0.009618129f, 0.05550411f);
    p = fmaf(f, p, 0.24022651f);
    p = fmaf(f, p, 0.69314718f);
    p = fmaf(f, p, 1.0f);                   // ~= 2^f
    return __int_as_float((__float_as_int(rr) << 23) + __float_as_int(p));
}

// ---------------------------------------------------------------------------
// 1) prep+pos: one block per augmentation pair (rows 2p, 2p+1).
// ---------------------------------------------------------------------------
__global__ void prep_kernel(const float* __restrict__ E, const int* __restrict__ labels) {
    int pair = blockIdx.x;
    int tid  = threadIdx.x;       // 128 threads
    int lane = tid & 31, wid = tid >> 5;

    const float4* A = reinterpret_cast<const float4*>(E + (size_t)(2 * pair) * DDIM);
    const float4* B = A + DDIM / 4;
    float4 a = A[tid], b = B[tid];
    float aa = a.x*a.x + a.y*a.y + a.z*a.z + a.w*a.w;
    float bb = b.x*b.x + b.y*b.y + b.z*b.z + b.w*b.w;
    float ab = a.x*b.x + a.y*b.y + a.z*b.z + a.w*b.w;
    #pragma unroll
    for (int off = 16; off > 0; off >>= 1) {
        aa += __shfl_down_sync(0xffffffffu, aa, off);
        bb += __shfl_down_sync(0xffffffffu, bb, off);
        ab += __shfl_down_sync(0xffffffffu, ab, off);
    }
    __shared__ float s_aa[4], s_bb[4], s_ab[4];
    if (lane == 0) { s_aa[wid] = aa; s_bb[wid] = bb; s_ab[wid] = ab; }
    __syncthreads();
    float taa = s_aa[0] + s_aa[1] + s_aa[2] + s_aa[3];
    float tbb = s_bb[0] + s_bb[1] + s_bb[2] + s_bb[3];
    float tab = s_ab[0] + s_ab[1] + s_ab[2] + s_ab[3];
    float sa = rsqrtf(taa) * SCALE_LOG2;
    float sb = rsqrtf(tbb) * SCALE_LOG2;

    size_t baseA = (size_t)(2 * pair) * KAUG + tid * 4;
    size_t baseB = baseA + KAUG;
    uint2 pa, pb;
    pa.x = h2_bits(__floats2half2_rn(a.x * sa, a.y * sa));
    pa.y = h2_bits(__floats2half2_rn(a.z * sa, a.w * sa));
    pb.x = h2_bits(__floats2half2_rn(b.x * sb, b.y * sb));
    pb.y = h2_bits(__floats2half2_rn(b.z * sb, b.w * sb));
    *reinterpret_cast<uint2*>(g_row + baseA) = pa;
    *reinterpret_cast<uint2*>(g_col + baseA) = pa;
    *reinterpret_cast<uint2*>(g_row + baseB) = pb;
    *reinterpret_cast<uint2*>(g_col + baseB) = pb;

    if (tid < 64) {
        int lab = labels[pair];
        __half hr = __float2half(tid == lab ? 16.0f : 0.0f);
        __half hc = __float2half(tid == lab ? -8.0f : 0.0f);
        size_t oA = (size_t)(2 * pair) * KAUG + DDIM + tid;
        g_row[oA] = hr;          g_col[oA] = hc;
        g_row[oA + KAUG] = hr;   g_col[oA + KAUG] = hc;
    }
    if (tid == 0) {
        g_pos[pair] = tab * rsqrtf(taa * tbb) * INV_T;
        if (pair == 0) { g_neg = 0.0; g_cnt = 0; }
    }
}

// ---------------------------------------------------------------------------
// 2) HMMA f16-acc GEMM: 128x128 CTA tile, 4 warps of 64x64 (best MMA:LDSM
//    ratio), 3-stage cp.async pipeline with ONE barrier per chunk, and
//    ldmatrix operand double-buffering across ks steps so the tensor pipe
//    never waits on smem latency. Fused exp2-sum epilogue; last CTA finishes.
// ---------------------------------------------------------------------------
__device__ __forceinline__ void load_chunk(uint32_t sb, int tid, int row0, int col0,
                                           int c, int stage) {
    #pragma unroll
    for (int itv = 0; itv < 16; itv++) {
        int slot = itv * 128 + tid;           // 0..2047 16B transfers
        int isB  = slot >> 10;
        int s2   = slot & 1023;
        int r    = s2 >> 3;                   // row in tile (0..127)
        int g    = s2 & 7;                    // 16B group in 128B row
        const __half* src = isB
            ? (g_col + (size_t)(col0 + r) * KAUG)
            : (g_row + (size_t)(row0 + r) * KAUG);
        src += c * KCHUNK + g * 8;
        uint32_t so = sb + stage * BUF_BYTES + isB * 16384
                    + (uint32_t)(r * 128) + (uint32_t)((g * 16) ^ ((r & 7) * 16));
        CP_ASYNC16(so, src);
    }
    CP_COMMIT();
}

__global__ void __launch_bounds__(128, 2) gemm_negsum_kernel(float* __restrict__ out) {
    extern __shared__ char smem[];
    __shared__ float red[4];
    __shared__ int   lastflag;
    uint32_t sb = smem_u32(smem);

    int tid  = threadIdx.x;
    int lane = tid & 31;
    int wid  = tid >> 5;

    // triangular tile decode
    int t = blockIdx.x, bi = 0, rem = NT;
    while (t >= rem) { t -= rem; rem--; bi++; }
    int bj = bi + t;
    int row0 = bi * BT, col0 = bj * BT;

    load_chunk(sb, tid, row0, col0, 0, 0);
    load_chunk(sb, tid, row0, col0, 1, 1);

    // warp tile: 64 (m) x 64 (n)
    int wm0 = (wid & 1) * 64;
    int wn0 = (wid >> 1) * 64;

    int arow = wm0 + (lane & 15);
    uint32_t a_xor = (uint32_t)((arow & 7) * 16);
    uint32_t a_colbase = (uint32_t)((lane >> 4) * 16);
    int brow = wn0 + ((lane >> 4) & 1) * 8 + (lane & 7);
    uint32_t b_xor = (uint32_t)((brow & 7) * 16);
    uint32_t b_colbase = (uint32_t)(((lane >> 3) & 1) * 16);

    uint32_t acc[4][8][2];                    // f16x2 accumulators (64x64)
    #pragma unroll
    for (int i = 0; i < 4; i++)
        #pragma unroll
        for (int j = 0; j < 8; j++) { acc[i][j][0] = 0u; acc[i][j][1] = 0u; }

    uint32_t aop[2][4][4], bop[2][4][4];      // double-buffered operands

    for (int c = 0; c < NCHUNKS; c++) {
        int stage = c % NSTAGES;
        if (c == NCHUNKS - 1) { CP_WAIT(0); } else { CP_WAIT(1); }
        __syncthreads();      // all warps done reading stage (c-1)%3; data c visible
        if (c + 2 < NCHUNKS) load_chunk(sb, tid, row0, col0, c + 2, (c + 2) % NSTAGES);

        uint32_t Ab = sb + (uint32_t)(stage * BUF_BYTES);
        uint32_t Bb = Ab + 16384;

        // prime ks=0 operands
        {
            uint32_t acol = a_colbase;
            #pragma unroll
            for (int mt = 0; mt < 4; mt++)
                ldmatrix_x4(aop[0][mt], Ab + (uint32_t)((arow + mt * 16) * 128) + (acol ^ a_xor));
            uint32_t bcol = b_colbase;
            #pragma unroll
            for (int p = 0; p < 4; p++)
                ldmatrix_x4(bop[0][p], Bb + (uint32_t)((brow + p * 16) * 128) + (bcol ^ b_xor));
        }

        #pragma unroll
        for (int ks = 0; ks < 4; ks++) {
            int cur = ks & 1, nxt = cur ^ 1;
            if (ks < 3) {   // prefetch next ks operands; hidden under 32 MMAs
                uint32_t acol = (uint32_t)((ks + 1) * 32) + a_colbase;
                #pragma unroll
                for (int mt = 0; mt < 4; mt++)
                    ldmatrix_x4(aop[nxt][mt], Ab + (uint32_t)((arow + mt * 16) * 128) + (acol ^ a_xor));
                uint32_t bcol = (uint32_t)((ks + 1) * 32) + b_colbase;
                #pragma unroll
                for (int p = 0; p < 4; p++)
                    ldmatrix_x4(bop[nxt][p], Bb + (uint32_t)((brow + p * 16) * 128) + (bcol ^ b_xor));
            }
            #pragma unroll
            for (int mt = 0; mt < 4; mt++)
                #pragma unroll
                for (int nt = 0; nt < 8; nt++)
                    mma16816_f16(acc[mt][nt], aop[cur][mt],
                                 bop[cur][nt >> 1][(nt & 1) * 2 + 0],
                                 bop[cur][nt >> 1][(nt & 1) * 2 + 1]);
        }
    }

    // ---- epilogue: exp2 over all 128 f16 accumulators ----
    float lsum = 0.0f;
    #pragma unroll
    for (int mt = 0; mt < 4; mt++)
        #pragma unroll
        for (int nt = 0; nt < 8; nt++)
            #pragma unroll
            for (int e = 0; e < 2; e++) {
                float2 v = __half22float2(*reinterpret_cast<__half2*>(&acc[mt][nt][e]));
                lsum += exp2_fast(v.x);
                lsum += exp2_fast(v.y);
            }
    if (bi == bj) lsum *= 0.5f;               // diagonal tile counts pairs twice

    #pragma unroll
    for (int off = 16; off > 0; off >>= 1) lsum += __shfl_down_sync(0xffffffffu, lsum, off);
    if (lane == 0) red[wid] = lsum;
    __syncthreads();
    if (tid == 0) {
        atomicAdd(&g_neg, (double)(red[0] + red[1] + red[2] + red[3]));
        __threadfence();
        lastflag = (atomicAdd(&g_cnt, 1) == NTILES - 1);
    }
    __syncthreads();

    // ---- last CTA computes the final loss ----
    if (lastflag) {
        __threadfence();
        float negf = (float)g_neg;
        float s = 0.0f;
        for (int p = tid; p < NPAIRS; p += 128) {
            float sp = g_pos[p];
            s += __logf(__expf(sp) + negf) - sp;
        }
        #pragma unroll
        for (int off = 16; off > 0; off >>= 1) s += __shfl_down_sync(0xffffffffu, s, off);
        if (lane == 0) red[wid] = s;
        __syncthreads();
        if (tid == 0) {
            out[0] = (red[0] + red[1] + red[2] + red[3]) / (float)NPAIRS;
            g_cnt = 0;
        }
    }
}

// ---------------------------------------------------------------------------
extern "C" void kernel_launch(void* const* d_in, const int* in_sizes, int n_in,
                              void* d_out, int out_size) {
    const float* E      = (const float*)d_in[0];
    const int*   labels = (const int*)d_in[1];
    float*       out    = (float*)d_out;

    const int SMEM_BYTES = NSTAGES * BUF_BYTES;   // 98304
    cudaFuncSetAttribute(gemm_negsum_kernel,
                         cudaFuncAttributeMaxDynamicSharedMemorySize, SMEM_BYTES);

    prep_kernel<<<NPAIRS, 128>>>(E, labels);
    gemm_negsum_kernel<<<NTILES, 128, SMEM_BYTES>>>(out);
}